// round 1
// baseline (speedup 1.0000x reference)
#include <cuda_runtime.h>
#include <math.h>

namespace {

constexpr int N = 64;
constexpr int THREADS = 256;
constexpr int NSWEEPS = 14;   // hard cap; early exit typically after ~7-8 sweeps

__device__ __forceinline__ float dot4(const float4 a, const float4 b) {
    return a.x * b.x + a.y * b.y + a.z * b.z + a.w * b.w;
}

__global__ void __launch_bounds__(THREADS)
logm_jacobi(const float* __restrict__ in, float* __restrict__ out) {
    __shared__ float W[N * N];      // column-major (== row-major: A symmetric)
    __shared__ float dsc[N];        // log(lambda)/lambda^2 per column
    __shared__ int any_rot;

    const int tid = threadIdx.x;
    const long long base = (long long)blockIdx.x * (N * N);

    // Load A into shared.
#pragma unroll
    for (int k = 0; k < (N * N) / THREADS; k++)
        W[tid + k * THREADS] = in[base + tid + k * THREADS];
    __syncthreads();

    const int pair = tid >> 3;      // 0..31 : column pair handled
    const int l8 = tid & 7;         // 0..7  : lane within pair
    const int roff = l8 << 3;       // 8 rows per lane

    for (int sweep = 0; sweep < NSWEEPS; sweep++) {
        if (tid == 0) any_rot = 0;
        __syncthreads();

        for (int r = 0; r < 63; r++) {
            // Circle-method round-robin pairing: covers all 2016 pairs per sweep.
            int x = r + pair; if (x >= 63) x -= 63;
            int y;
            if (pair == 0) { y = 63; }
            else { y = r - pair; if (y < 0) y += 63; }

            float4* cp = reinterpret_cast<float4*>(&W[x * N + roff]);
            float4* cq = reinterpret_cast<float4*>(&W[y * N + roff]);
            float4 p0 = cp[0], p1 = cp[1];
            float4 q0 = cq[0], q1 = cq[1];

            float aa = dot4(p0, p0) + dot4(p1, p1);
            float bb = dot4(q0, q0) + dot4(q1, q1);
            float gg = dot4(p0, q0) + dot4(p1, q1);
#pragma unroll
            for (int o = 4; o > 0; o >>= 1) {
                aa += __shfl_down_sync(0xffffffffu, aa, o, 8);
                bb += __shfl_down_sync(0xffffffffu, bb, o, 8);
                gg += __shfl_down_sync(0xffffffffu, gg, o, 8);
            }
            aa = __shfl_sync(0xffffffffu, aa, 0, 8);
            bb = __shfl_sync(0xffffffffu, bb, 0, 8);
            gg = __shfl_sync(0xffffffffu, gg, 0, 8);

            // Skip numerically negligible rotations (|g| <= ~4.5e-7 * sqrt(a*b)).
            if (gg * gg > 2e-13f * aa * bb) {
                if (l8 == 0) any_rot = 1;
                float zeta = (bb - aa) / (2.0f * gg);
                float t = copysignf(1.0f, zeta) /
                          (fabsf(zeta) + sqrtf(1.0f + zeta * zeta));
                float c = rsqrtf(1.0f + t * t);
                float s = c * t;

                float4 u, v;
                u.x = c * p0.x - s * q0.x;  v.x = s * p0.x + c * q0.x;
                u.y = c * p0.y - s * q0.y;  v.y = s * p0.y + c * q0.y;
                u.z = c * p0.z - s * q0.z;  v.z = s * p0.z + c * q0.z;
                u.w = c * p0.w - s * q0.w;  v.w = s * p0.w + c * q0.w;
                cp[0] = u; cq[0] = v;
                u.x = c * p1.x - s * q1.x;  v.x = s * p1.x + c * q1.x;
                u.y = c * p1.y - s * q1.y;  v.y = s * p1.y + c * q1.y;
                u.z = c * p1.z - s * q1.z;  v.z = s * p1.z + c * q1.z;
                u.w = c * p1.w - s * q1.w;  v.w = s * p1.w + c * q1.w;
                cp[1] = u; cq[1] = v;
            }
            __syncthreads();
        }
        // All writes visible (round loop ends with a barrier). Uniform break.
        if (any_rot == 0) break;
        __syncthreads();  // protect the read above from next sweep's reset
    }

    // Eigenvalues = column norms of W (W = U * Sigma); build scale factors.
    {
        const int col = tid >> 2;
        const int l4 = tid & 3;
        const float4* cw = reinterpret_cast<const float4*>(&W[col * N + l4 * 16]);
        float ss = 0.0f;
#pragma unroll
        for (int k = 0; k < 4; k++) { float4 v = cw[k]; ss += dot4(v, v); }
        ss += __shfl_down_sync(0xffffffffu, ss, 2, 4);
        ss += __shfl_down_sync(0xffffffffu, ss, 1, 4);
        if (l4 == 0) {
            float lam = sqrtf(ss);                     // eigenvalue
            dsc[col] = logf(lam + 1e-9f) / ss;         // log(relu(l)+eps)/l^2
        }
    }
    __syncthreads();

    // out = W * diag(dsc) * W^T : 4x4 register tile per thread (16x16 thread grid).
    {
        const int tr = tid >> 4;
        const int tc = tid & 15;
        const int r0 = tr << 2;
        const int c0 = tc << 2;
        float acc[4][4] = {};
#pragma unroll 4
        for (int j = 0; j < N; j++) {
            const float dj = dsc[j];
            float4 uu = *reinterpret_cast<const float4*>(&W[j * N + r0]);
            float4 vv = *reinterpret_cast<const float4*>(&W[j * N + c0]);
            float ua[4] = {uu.x * dj, uu.y * dj, uu.z * dj, uu.w * dj};
            float vb[4] = {vv.x, vv.y, vv.z, vv.w};
#pragma unroll
            for (int i = 0; i < 4; i++)
#pragma unroll
                for (int k2 = 0; k2 < 4; k2++)
                    acc[i][k2] += ua[i] * vb[k2];
        }
#pragma unroll
        for (int i = 0; i < 4; i++) {
            float4 o4 = make_float4(acc[i][0], acc[i][1], acc[i][2], acc[i][3]);
            *reinterpret_cast<float4*>(&out[base + (long long)(r0 + i) * N + c0]) = o4;
        }
    }
}

}  // namespace

extern "C" void kernel_launch(void* const* d_in, const int* in_sizes, int n_in,
                              void* d_out, int out_size) {
    const float* in = (const float*)d_in[0];
    float* out = (float*)d_out;
    const int nmat = in_sizes[0] / (N * N);   // 256*32 = 8192 matrices
    logm_jacobi<<<nmat, THREADS>>>(in, out);
}

// round 4
// speedup vs baseline: 1.2425x; 1.2425x over previous
#include <cuda_runtime.h>
#include <math.h>

namespace {

constexpr int N = 64;
constexpr int THREADS = 256;
constexpr int NSWEEPS = 18;      // cap; early exit on convergence
constexpr float TAU2 = 1e-12f;   // skip rotation if g^2 <= TAU2 * np * nq

using u64 = unsigned long long;

// ---- packed f32x2 helpers (sm_103a dual-rate fp32) ----
__device__ __forceinline__ u64 pk(float lo, float hi) {
    u64 r; asm("mov.b64 %0,{%1,%2};" : "=l"(r) : "f"(lo), "f"(hi)); return r;
}
__device__ __forceinline__ void upk(u64 v, float& lo, float& hi) {
    asm("mov.b64 {%0,%1},%2;" : "=f"(lo), "=f"(hi) : "l"(v));
}
__device__ __forceinline__ u64 mul2(u64 a, u64 b) {
    u64 r; asm("mul.rn.f32x2 %0,%1,%2;" : "=l"(r) : "l"(a), "l"(b)); return r;
}
__device__ __forceinline__ u64 fma2(u64 a, u64 b, u64 c) {
    u64 r; asm("fma.rn.f32x2 %0,%1,%2,%3;" : "=l"(r) : "l"(a), "l"(b), "l"(c)); return r;
}

// One column slice: 8 rows (8*l8 .. 8*l8+7) as 4 packed f32x2.
struct Col { u64 a, b, c, d; };

__device__ __forceinline__ float dot8(const Col& x, const Col& y) {
    u64 t = mul2(x.a, y.a);
    t = fma2(x.b, y.b, t);
    t = fma2(x.c, y.c, t);
    t = fma2(x.d, y.d, t);
    float lo, hi; upk(t, lo, hi);
    return lo + hi;
}
// sum across the 8-lane slot; result in all 8 lanes
__device__ __forceinline__ float red8(float v) {
    v += __shfl_xor_sync(0xffffffffu, v, 4);
    v += __shfl_xor_sync(0xffffffffu, v, 2);
    v += __shfl_xor_sync(0xffffffffu, v, 1);
    return v;
}
__device__ __forceinline__ Col axpby(const Col& p, const Col& q, float cp, float cq) {
    u64 c2 = pk(cp, cp), d2 = pk(cq, cq);
    Col r;
    r.a = fma2(p.a, c2, mul2(q.a, d2));
    r.b = fma2(p.b, c2, mul2(q.b, d2));
    r.c = fma2(p.c, c2, mul2(q.c, d2));
    r.d = fma2(p.d, c2, mul2(q.d, d2));
    return r;
}
__device__ __forceinline__ Col shfl_up8(const Col& x) {
    Col r;
    r.a = __shfl_up_sync(0xffffffffu, x.a, 8);
    r.b = __shfl_up_sync(0xffffffffu, x.b, 8);
    r.c = __shfl_up_sync(0xffffffffu, x.c, 8);
    r.d = __shfl_up_sync(0xffffffffu, x.d, 8);
    return r;
}
__device__ __forceinline__ Col shfl_dn8(const Col& x) {
    Col r;
    r.a = __shfl_down_sync(0xffffffffu, x.a, 8);
    r.b = __shfl_down_sync(0xffffffffu, x.b, 8);
    r.c = __shfl_down_sync(0xffffffffu, x.c, 8);
    r.d = __shfl_down_sync(0xffffffffu, x.d, 8);
    return r;
}

__global__ void __launch_bounds__(THREADS)
logm_rr(const float* __restrict__ in, float* __restrict__ out) {
    // mailboxes: [buf(2)][kind T=0..7 / B=8..15][72 floats: 64 col + norm + pad]
    __shared__ __align__(16) float W[N * N];
    __shared__ __align__(16) float mail[2 * 16 * 72];
    __shared__ float dsc[N];
    __shared__ int any_rot;

    const int tid = threadIdx.x;
    const int s  = tid >> 3;        // slot 0..31
    const int l8 = tid & 7;         // lane within slot
    const int w  = tid >> 5;        // warp 0..7
    const int sl = s & 3;           // slot within warp 0..3
    const long long base = (long long)blockIdx.x * (N * N);

    // Load columns 2s (T) and 2s+1 (B) into registers.
    const float4* inp = reinterpret_cast<const float4*>(in + base);
    float4 a0 = inp[(2 * s) * 16 + 2 * l8];
    float4 a1 = inp[(2 * s) * 16 + 2 * l8 + 1];
    float4 b0 = inp[(2 * s + 1) * 16 + 2 * l8];
    float4 b1 = inp[(2 * s + 1) * 16 + 2 * l8 + 1];
    Col T = { pk(a0.x, a0.y), pk(a0.z, a0.w), pk(a1.x, a1.y), pk(a1.z, a1.w) };
    Col B = { pk(b0.x, b0.y), pk(b0.z, b0.w), pk(b1.x, b1.y), pk(b1.z, b1.w) };
    float nT = 0.0f, nB = 0.0f;

    int rc = 0;  // running round counter -> mailbox buffer parity

    for (int sweep = 0; sweep < NSWEEPS; sweep++) {
        if (tid == 0) any_rot = 0;
        // refresh norms exactly each sweep (kills incremental drift)
        nT = red8(dot8(T, T));
        nB = red8(dot8(B, B));
        __syncthreads();   // reset visible before rounds set the flag

        for (int r = 0; r < 63; r++) {
            // ---- rotate local pair (T, B) ----
            float gg = red8(dot8(T, B));
            if (gg * gg > TAU2 * nT * nB) {
                float zeta = __fdividef(nB - nT, 2.0f * gg);
                float t = __fdividef(copysignf(1.0f, zeta),
                                     fabsf(zeta) + sqrtf(fmaf(zeta, zeta, 1.0f)));
                float c = rsqrtf(fmaf(t, t, 1.0f));
                float sn = c * t;
                Col Tn = axpby(T, B, c, -sn);
                Col Bn = axpby(T, B, sn, c);
                T = Tn; B = Bn;
                nT = nT - t * gg;
                nB = nB + t * gg;
                if (l8 == 0) any_rot = 1;
            }

            // ---- circle-method movement ----
            // T_0 fixed; B_0->T_1; T_s->T_{s+1}; T_31->B_31; B_{s+1}->B_s
            const int buf = rc & 1; rc++;
            if (sl == 3 && w < 7) {          // T crosses warp boundary upward
                u64* d = (u64*)(mail + (buf * 16 + w) * 72);
                d[4 * l8] = T.a; d[4 * l8 + 1] = T.b;
                d[4 * l8 + 2] = T.c; d[4 * l8 + 3] = T.d;
                if (l8 == 0) ((float*)d)[64] = nT;
            }
            if (sl == 0 && w > 0) {          // B crosses warp boundary downward
                u64* d = (u64*)(mail + (buf * 16 + 8 + w) * 72);
                d[4 * l8] = B.a; d[4 * l8 + 1] = B.b;
                d[4 * l8 + 2] = B.c; d[4 * l8 + 3] = B.d;
                if (l8 == 0) ((float*)d)[64] = nB;
            }
            __syncthreads();

            // within-warp shifts (slot 0 of warp 0 feeds its B into T_1)
            const bool feedB = (w == 0 && sl == 0);
            Col vs = feedB ? B : T;
            float vn = feedB ? nB : nT;
            Col  tNew = shfl_up8(vs);
            float tnNew = __shfl_up_sync(0xffffffffu, vn, 8);
            Col  bNew = shfl_dn8(B);
            float bnNew = __shfl_down_sync(0xffffffffu, nB, 8);

            if (sl == 0) {
                if (w == 0) { tNew = T; tnNew = nT; }              // T_0 fixed
                else {
                    const u64* sp = (const u64*)(mail + (buf * 16 + (w - 1)) * 72);
                    tNew.a = sp[4 * l8];     tNew.b = sp[4 * l8 + 1];
                    tNew.c = sp[4 * l8 + 2]; tNew.d = sp[4 * l8 + 3];
                    tnNew = ((const float*)sp)[64];
                }
            }
            if (sl == 3) {
                if (w == 7) { bNew = T; bnNew = nT; }              // T_31 -> B_31
                else {
                    const u64* sp = (const u64*)(mail + (buf * 16 + 8 + (w + 1)) * 72);
                    bNew.a = sp[4 * l8];     bNew.b = sp[4 * l8 + 1];
                    bNew.c = sp[4 * l8 + 2]; bNew.d = sp[4 * l8 + 3];
                    bnNew = ((const float*)sp)[64];
                }
            }
            T = tNew; nT = tnNew;
            B = bNew; nB = bnNew;
        }

        __syncthreads();            // all any_rot sets visible
        int done = (any_rot == 0);  // everyone reads
        __syncthreads();            // reads complete before next reset
        if (done) break;
    }

    // ---- finalize: exact norms, store W + dsc ----
    float ssT = red8(dot8(T, T));
    float ssB = red8(dot8(B, B));
    {
        u64* d1 = (u64*)(W + (2 * s) * N);
        d1[4 * l8] = T.a; d1[4 * l8 + 1] = T.b;
        d1[4 * l8 + 2] = T.c; d1[4 * l8 + 3] = T.d;
        u64* d2 = (u64*)(W + (2 * s + 1) * N);
        d2[4 * l8] = B.a; d2[4 * l8 + 1] = B.b;
        d2[4 * l8 + 2] = B.c; d2[4 * l8 + 3] = B.d;
        if (l8 == 0) {
            // eigenvalue lam = sqrt(ss); scale = log(lam + eps) / lam^2
            float sT = fmaxf(ssT, 1e-30f);
            dsc[2 * s] = __fdividef(logf(sqrtf(sT) + 1e-9f), sT);
            float sB = fmaxf(ssB, 1e-30f);
            dsc[2 * s + 1] = __fdividef(logf(sqrtf(sB) + 1e-9f), sB);
        }
    }
    __syncthreads();

    // ---- out = W diag(dsc) W^T : 4x4 tile per thread, packed f32x2 ----
    {
        const int tr = tid >> 4, tc = tid & 15;
        const int r0 = tr << 2, c0 = tc << 2;
        u64 acc[4][2] = {};
#pragma unroll 4
        for (int j = 0; j < N; j++) {
            const float dj = dsc[j];
            float4 uu = *reinterpret_cast<const float4*>(&W[j * N + r0]);
            float4 vv = *reinterpret_cast<const float4*>(&W[j * N + c0]);
            u64 v01 = pk(vv.x, vv.y), v23 = pk(vv.z, vv.w);
            float u0 = uu.x * dj, u1 = uu.y * dj, u2 = uu.z * dj, u3 = uu.w * dj;
            u64 U;
            U = pk(u0, u0); acc[0][0] = fma2(U, v01, acc[0][0]); acc[0][1] = fma2(U, v23, acc[0][1]);
            U = pk(u1, u1); acc[1][0] = fma2(U, v01, acc[1][0]); acc[1][1] = fma2(U, v23, acc[1][1]);
            U = pk(u2, u2); acc[2][0] = fma2(U, v01, acc[2][0]); acc[2][1] = fma2(U, v23, acc[2][1]);
            U = pk(u3, u3); acc[3][0] = fma2(U, v01, acc[3][0]); acc[3][1] = fma2(U, v23, acc[3][1]);
        }
#pragma unroll
        for (int i = 0; i < 4; i++) {
            float x, y, z, ww;
            upk(acc[i][0], x, y);
            upk(acc[i][1], z, ww);
            *reinterpret_cast<float4*>(&out[base + (long long)(r0 + i) * N + c0]) =
                make_float4(x, y, z, ww);
        }
    }
}

}  // namespace

extern "C" void kernel_launch(void* const* d_in, const int* in_sizes, int n_in,
                              void* d_out, int out_size) {
    const float* in = (const float*)d_in[0];
    float* out = (float*)d_out;
    const int nmat = in_sizes[0] / (N * N);   // 8192 matrices
    logm_rr<<<nmat, THREADS>>>(in, out);
}

// round 5
// speedup vs baseline: 2.3942x; 1.9270x over previous
#include <cuda_runtime.h>
#include <math.h>

namespace {

constexpr int N = 64;
constexpr int WARPS = 10;
constexpr int THREADS = WARPS * 32;
constexpr int NSWEEPS = 18;
constexpr float TAU = 1e-6f;       // rotate if |g_hat| > TAU * sqrt(nT*nB) (scale-free)
constexpr int CPAD = 68;           // floats per column slot in shared (16B-aligned stride)
constexpr unsigned FULL = 0xffffffffu;

using u64 = unsigned long long;

__device__ __forceinline__ u64 pk(float lo, float hi) {
    u64 r; asm("mov.b64 %0,{%1,%2};" : "=l"(r) : "f"(lo), "f"(hi)); return r;
}
__device__ __forceinline__ void upk(u64 v, float& lo, float& hi) {
    asm("mov.b64 {%0,%1},%2;" : "=f"(lo), "=f"(hi) : "l"(v));
}
__device__ __forceinline__ u64 mul2(u64 a, u64 b) {
    u64 r; asm("mul.rn.f32x2 %0,%1,%2;" : "=l"(r) : "l"(a), "l"(b)); return r;
}
__device__ __forceinline__ u64 fma2(u64 a, u64 b, u64 c) {
    u64 r; asm("fma.rn.f32x2 %0,%1,%2,%3;" : "=l"(r) : "l"(a), "l"(b), "l"(c)); return r;
}
__device__ __forceinline__ float psum(u64 v) {
    float lo, hi; upk(v, lo, hi); return lo + hi;
}

__global__ void __launch_bounds__(THREADS, 1)
logm_warpjac(const float* __restrict__ in, float* __restrict__ out, int nmat) {
    extern __shared__ float sm[];

    const int lane = threadIdx.x & 31;
    const int wid = threadIdx.x >> 5;
    const int m = blockIdx.x * WARPS + wid;
    if (m >= nmat) return;                      // whole-warp uniform; no CTA syncs anywhere

    float* Wsh = sm + wid * (N * CPAD);
    const float* A = in + (long long)m * (N * N);

    // Lane holds 2 full columns as 32 packed f32x2 each.
    u64 T[32], B[32];
    {
        const float4* p = reinterpret_cast<const float4*>(A + (2 * lane) * N);
        const float4* q = reinterpret_cast<const float4*>(A + (2 * lane + 1) * N);
#pragma unroll
        for (int k = 0; k < 16; k++) {
            float4 v = p[k];
            T[2 * k] = pk(v.x, v.y); T[2 * k + 1] = pk(v.z, v.w);
            float4 w = q[k];
            B[2 * k] = pk(w.x, w.y); B[2 * k + 1] = pk(w.z, w.w);
        }
    }
    float sT = 1.0f, sB = 1.0f;   // column scale factors (fast rotations)
    float nT = 0.0f, nB = 0.0f;   // scaled squared norms: actual = s^2 * n

    for (int sweep = 0; sweep < NSWEEPS; sweep++) {
        // fold scales + exact norm refresh (kills drift; bounds scale range)
        {
            u64 s1 = pk(sT, sT), s2 = pk(sB, sB);
            u64 a0 = pk(0.f, 0.f), a1 = a0, b0 = a0, b1 = a0;
#pragma unroll
            for (int k = 0; k < 16; k++) {
                T[2 * k] = mul2(T[2 * k], s1); T[2 * k + 1] = mul2(T[2 * k + 1], s1);
                B[2 * k] = mul2(B[2 * k], s2); B[2 * k + 1] = mul2(B[2 * k + 1], s2);
                a0 = fma2(T[2 * k], T[2 * k], a0); a1 = fma2(T[2 * k + 1], T[2 * k + 1], a1);
                b0 = fma2(B[2 * k], B[2 * k], b0); b1 = fma2(B[2 * k + 1], B[2 * k + 1], b1);
            }
            sT = 1.0f; sB = 1.0f;
            nT = psum(a0) + psum(a1);
            nB = psum(b0) + psum(b1);
        }
        bool any = false;

        for (int it = 0; it < 32; it++) {
            // ================= even round: local pair (T, B) =================
            {
                u64 g0 = pk(0.f, 0.f), g1 = g0;
#pragma unroll
                for (int k = 0; k < 16; k++) {
                    g0 = fma2(T[2 * k], B[2 * k], g0);
                    g1 = fma2(T[2 * k + 1], B[2 * k + 1], g1);
                }
                float gh = psum(g0) + psum(g1);

                float alpha = 0.f, beta = 0.f, c = 1.f, rc2 = 1.f;
                bool rot = fabsf(gh) > TAU * sqrtf(nT) * sqrtf(nB);
                if (rot) {
                    float ga = sT * sB * gh;
                    float nTa = sT * sT * nT, nBa = sB * sB * nB;
                    float zeta = __fdividef(nBa - nTa, 2.0f * ga);
                    float tt = __fdividef(copysignf(1.0f, zeta),
                                          fabsf(zeta) + sqrtf(fmaf(zeta, zeta, 1.0f)));
                    c = rsqrtf(fmaf(tt, tt, 1.0f));
                    rc2 = fmaf(tt, tt, 1.0f);
                    float r = __fdividef(sB, sT);
                    alpha = tt * r;                 // T' = T - alpha*B
                    beta  = __fdividef(tt, r);      // B' = B + beta*T
                    any = true;
                }
                // outputs swapped: top <- B', bottom <- T'  (skip => pure swap)
                u64 b2 = pk(beta, beta), na2 = pk(-alpha, -alpha);
#pragma unroll
                for (int k = 0; k < 32; k++) {
                    u64 t0 = T[k];
                    T[k] = fma2(t0, b2, B[k]);
                    B[k] = fma2(B[k], na2, t0);
                }
                float nTn = (nB + beta * gh) * rc2;
                float nBn = (nT - alpha * gh) * rc2;
                float sTn = sB * c, sBn = sT * c;
                sT = sTn; sB = sBn; nT = nTn; nB = nBn;
            }
            // ============ odd round: pair (B_t, T_{t+1}); lane31 idle ============
            {
                // pass 1: dot(B, T_shifted)
                u64 g0 = pk(0.f, 0.f), g1 = g0;
#pragma unroll
                for (int k = 0; k < 16; k++) {
                    u64 t0 = __shfl_down_sync(FULL, T[2 * k], 1);
                    u64 t1 = __shfl_down_sync(FULL, T[2 * k + 1], 1);
                    g0 = fma2(B[2 * k], t0, g0);
                    g1 = fma2(B[2 * k + 1], t1, g1);
                }
                float gh = psum(g0) + psum(g1);
                float sTm = __shfl_down_sync(FULL, sT, 1);
                float nTm = __shfl_down_sync(FULL, nT, 1);

                float alpha = 0.f, beta = 0.f, c = 1.f, rc2 = 1.f;
                bool rot = (lane < 31) &&
                           (fabsf(gh) > TAU * sqrtf(nB) * sqrtf(nTm));
                if (rot) {
                    float ga = sB * sTm * gh;
                    float nPa = sB * sB * nB, nQa = sTm * sTm * nTm;
                    float zeta = __fdividef(nQa - nPa, 2.0f * ga);
                    float tt = __fdividef(copysignf(1.0f, zeta),
                                          fabsf(zeta) + sqrtf(fmaf(zeta, zeta, 1.0f)));
                    c = rsqrtf(fmaf(tt, tt, 1.0f));
                    rc2 = fmaf(tt, tt, 1.0f);
                    float r = __fdividef(sTm, sB);
                    alpha = tt * r;                 // ship = B - alpha*Tm
                    beta  = __fdividef(tt, r);      // keep = Tm + beta*B
                    any = true;
                }
                // pass 2: recompute shift, rotate, ship P' up; keep Q' locally
                u64 b2 = pk(beta, beta), na2 = pk(-alpha, -alpha);
#pragma unroll
                for (int k = 0; k < 32; k++) {
                    u64 tm = __shfl_down_sync(FULL, T[k], 1);
                    u64 sh = fma2(tm, na2, B[k]);     // P' (goes up to lane+1's top)
                    u64 bn = fma2(B[k], b2, tm);      // Q' (stays as bottom)
                    u64 rc = __shfl_up_sync(FULL, sh, 1);
                    if (lane < 31) B[k] = bn;
                    if (lane >= 1) T[k] = rc;
                }
                float shipS = sB * c, shipN = (nB - alpha * gh) * rc2;
                float keepS = sTm * c, keepN = (nTm + beta * gh) * rc2;
                float rS = __shfl_up_sync(FULL, shipS, 1);
                float rN = __shfl_up_sync(FULL, shipN, 1);
                if (lane < 31) { sB = keepS; nB = keepN; }
                if (lane >= 1) { sT = rS; nT = rN; }
            }
        }
        if (!__any_sync(FULL, any)) break;
    }

    // ---- finalize: fold scales, exact norms, stash W + dsc in shared ----
    float ssT, ssB;
    {
        u64 s1 = pk(sT, sT), s2 = pk(sB, sB);
        u64 a0 = pk(0.f, 0.f), a1 = a0, b0 = a0, b1 = a0;
#pragma unroll
        for (int k = 0; k < 16; k++) {
            T[2 * k] = mul2(T[2 * k], s1); T[2 * k + 1] = mul2(T[2 * k + 1], s1);
            B[2 * k] = mul2(B[2 * k], s2); B[2 * k + 1] = mul2(B[2 * k + 1], s2);
            a0 = fma2(T[2 * k], T[2 * k], a0); a1 = fma2(T[2 * k + 1], T[2 * k + 1], a1);
            b0 = fma2(B[2 * k], B[2 * k], b0); b1 = fma2(B[2 * k + 1], B[2 * k + 1], b1);
        }
        ssT = psum(a0) + psum(a1);
        ssB = psum(b0) + psum(b1);
    }
    {
        u64* c0 = reinterpret_cast<u64*>(Wsh + (2 * lane) * CPAD);
        u64* c1 = reinterpret_cast<u64*>(Wsh + (2 * lane + 1) * CPAD);
#pragma unroll
        for (int k = 0; k < 32; k++) { c0[k] = T[k]; c1[k] = B[k]; }
        float s0 = fmaxf(ssT, 1e-30f);
        Wsh[(2 * lane) * CPAD + 64] = __fdividef(logf(sqrtf(s0) + 1e-9f), s0);
        float s1 = fmaxf(ssB, 1e-30f);
        Wsh[(2 * lane + 1) * CPAD + 64] = __fdividef(logf(sqrtf(s1) + 1e-9f), s1);
    }
    __syncwarp();

    // ---- out = sum_c dsc_c * w_c w_c^T : lane computes rows 2*lane, 2*lane+1 ----
    {
        u64 a0[32], a1[32];
#pragma unroll
        for (int k = 0; k < 32; k++) { a0[k] = pk(0.f, 0.f); a1[k] = pk(0.f, 0.f); }
#pragma unroll 4
        for (int cidx = 0; cidx < N; cidx++) {
            const float* col = Wsh + cidx * CPAD;
            float dc = col[64];
            float2 wi = *reinterpret_cast<const float2*>(col + 2 * lane);
            float u0 = wi.x * dc, u1 = wi.y * dc;
            u64 u02 = pk(u0, u0), u12 = pk(u1, u1);
#pragma unroll
            for (int k = 0; k < 16; k++) {
                ulonglong2 q = *reinterpret_cast<const ulonglong2*>(col + 4 * k);
                a0[2 * k]     = fma2(u02, q.x, a0[2 * k]);
                a0[2 * k + 1] = fma2(u02, q.y, a0[2 * k + 1]);
                a1[2 * k]     = fma2(u12, q.x, a1[2 * k]);
                a1[2 * k + 1] = fma2(u12, q.y, a1[2 * k + 1]);
            }
        }
        float* o0 = out + (long long)m * (N * N) + (2 * lane) * N;
        float* o1 = o0 + N;
#pragma unroll
        for (int k = 0; k < 16; k++) {
            ulonglong2 v0; v0.x = a0[2 * k]; v0.y = a0[2 * k + 1];
            *reinterpret_cast<ulonglong2*>(o0 + 4 * k) = v0;
            ulonglong2 v1; v1.x = a1[2 * k]; v1.y = a1[2 * k + 1];
            *reinterpret_cast<ulonglong2*>(o1 + 4 * k) = v1;
        }
    }
}

}  // namespace

extern "C" void kernel_launch(void* const* d_in, const int* in_sizes, int n_in,
                              void* d_out, int out_size) {
    const float* in = (const float*)d_in[0];
    float* out = (float*)d_out;
    const int nmat = in_sizes[0] / (N * N);   // 8192
    const int smem = WARPS * N * CPAD * (int)sizeof(float);   // 174,080 B
    cudaFuncSetAttribute(logm_warpjac, cudaFuncAttributeMaxDynamicSharedMemorySize, smem);
    const int grid = (nmat + WARPS - 1) / WARPS;
    logm_warpjac<<<grid, THREADS, smem>>>(in, out, nmat);
}

// round 7
// speedup vs baseline: 2.7322x; 1.1412x over previous
#include <cuda_runtime.h>
#include <math.h>

namespace {

constexpr int N = 64;
constexpr int WARPS = 12;
constexpr int THREADS = WARPS * 32;
constexpr int NSWEEPS = 18;
constexpr float TAU = 2e-5f;       // rotate if |g_hat| > TAU * sqrt(nT*nB) (scale-free)
constexpr int CPAD = 68;           // floats per column slot in shared (16B-aligned stride)
constexpr unsigned FULL = 0xffffffffu;

using u64 = unsigned long long;

__device__ __forceinline__ u64 pk(float lo, float hi) {
    u64 r; asm("mov.b64 %0,{%1,%2};" : "=l"(r) : "f"(lo), "f"(hi)); return r;
}
__device__ __forceinline__ void upk(u64 v, float& lo, float& hi) {
    asm("mov.b64 {%0,%1},%2;" : "=f"(lo), "=f"(hi) : "l"(v));
}
__device__ __forceinline__ u64 mul2(u64 a, u64 b) {
    u64 r; asm("mul.rn.f32x2 %0,%1,%2;" : "=l"(r) : "l"(a), "l"(b)); return r;
}
__device__ __forceinline__ u64 fma2(u64 a, u64 b, u64 c) {
    u64 r; asm("fma.rn.f32x2 %0,%1,%2,%3;" : "=l"(r) : "l"(a), "l"(b), "l"(c)); return r;
}
__device__ __forceinline__ float psum(u64 v) {
    float lo, hi; upk(v, lo, hi); return lo + hi;
}

__global__ void __launch_bounds__(THREADS, 1)
logm_warpjac(const float* __restrict__ in, float* __restrict__ out, int nmat) {
    extern __shared__ float sm[];

    const int lane = threadIdx.x & 31;
    const int wid = threadIdx.x >> 5;
    const int m = blockIdx.x * WARPS + wid;
    if (m >= nmat) return;                      // whole-warp uniform; no CTA syncs anywhere

    float* Wsh = sm + wid * (N * CPAD);
    const float* A = in + (long long)m * (N * N);

    // Lane holds 2 full columns as 32 packed f32x2 each.
    u64 T[32], B[32];
    {
        const float4* p = reinterpret_cast<const float4*>(A + (2 * lane) * N);
        const float4* q = reinterpret_cast<const float4*>(A + (2 * lane + 1) * N);
#pragma unroll
        for (int k = 0; k < 16; k++) {
            float4 v = p[k];
            T[2 * k] = pk(v.x, v.y); T[2 * k + 1] = pk(v.z, v.w);
            float4 w = q[k];
            B[2 * k] = pk(w.x, w.y); B[2 * k + 1] = pk(w.z, w.w);
        }
    }
    float sT = 1.0f, sB = 1.0f;   // column scale factors (fast rotations)
    float nT = 0.0f, nB = 0.0f;   // scaled squared norms: actual = s^2 * n

    for (int sweep = 0; sweep < NSWEEPS; sweep++) {
        // fold scales + exact norm refresh (kills drift; bounds scale range)
        {
            u64 s1 = pk(sT, sT), s2 = pk(sB, sB);
            u64 a0 = pk(0.f, 0.f), a1 = a0, a2 = a0, a3 = a0;
            u64 b0 = a0, b1 = a0, b2a = a0, b3 = a0;
#pragma unroll
            for (int k = 0; k < 8; k++) {
                T[4 * k]     = mul2(T[4 * k], s1);     T[4 * k + 1] = mul2(T[4 * k + 1], s1);
                T[4 * k + 2] = mul2(T[4 * k + 2], s1); T[4 * k + 3] = mul2(T[4 * k + 3], s1);
                B[4 * k]     = mul2(B[4 * k], s2);     B[4 * k + 1] = mul2(B[4 * k + 1], s2);
                B[4 * k + 2] = mul2(B[4 * k + 2], s2); B[4 * k + 3] = mul2(B[4 * k + 3], s2);
                a0 = fma2(T[4 * k],     T[4 * k],     a0);
                a1 = fma2(T[4 * k + 1], T[4 * k + 1], a1);
                a2 = fma2(T[4 * k + 2], T[4 * k + 2], a2);
                a3 = fma2(T[4 * k + 3], T[4 * k + 3], a3);
                b0 = fma2(B[4 * k],     B[4 * k],     b0);
                b1 = fma2(B[4 * k + 1], B[4 * k + 1], b1);
                b2a = fma2(B[4 * k + 2], B[4 * k + 2], b2a);
                b3 = fma2(B[4 * k + 3], B[4 * k + 3], b3);
            }
            sT = 1.0f; sB = 1.0f;
            nT = psum(a0) + psum(a1) + psum(a2) + psum(a3);
            nB = psum(b0) + psum(b1) + psum(b2a) + psum(b3);
        }
        bool any = false;

        for (int it = 0; it < 32; it++) {
            // ================= even round: local pair (T, B) =================
            {
                u64 g0 = pk(0.f, 0.f), g1 = g0, g2 = g0, g3 = g0;
#pragma unroll
                for (int k = 0; k < 8; k++) {
                    g0 = fma2(T[4 * k],     B[4 * k],     g0);
                    g1 = fma2(T[4 * k + 1], B[4 * k + 1], g1);
                    g2 = fma2(T[4 * k + 2], B[4 * k + 2], g2);
                    g3 = fma2(T[4 * k + 3], B[4 * k + 3], g3);
                }
                float gh = psum(g0) + psum(g1) + psum(g2) + psum(g3);

                float alpha = 0.f, beta = 0.f, c = 1.f, rc2 = 1.f;
                bool rot = fabsf(gh) > TAU * sqrtf(nT) * sqrtf(nB);
                if (rot) {
                    float ga = sT * sB * gh;
                    float nTa = sT * sT * nT, nBa = sB * sB * nB;
                    float zeta = __fdividef(nBa - nTa, 2.0f * ga);
                    float tt = __fdividef(copysignf(1.0f, zeta),
                                          fabsf(zeta) + sqrtf(fmaf(zeta, zeta, 1.0f)));
                    c = rsqrtf(fmaf(tt, tt, 1.0f));
                    rc2 = fmaf(tt, tt, 1.0f);
                    float r = __fdividef(sB, sT);
                    alpha = tt * r;                 // T' = T - alpha*B
                    beta  = __fdividef(tt, r);      // B' = B + beta*T
                    any = true;
                }
                // outputs swapped: top <- B', bottom <- T'  (skip => pure swap)
                u64 b2 = pk(beta, beta), na2 = pk(-alpha, -alpha);
#pragma unroll
                for (int k = 0; k < 32; k++) {
                    u64 t0 = T[k];
                    T[k] = fma2(t0, b2, B[k]);
                    B[k] = fma2(B[k], na2, t0);
                }
                float nTn = (nB + beta * gh) * rc2;
                float nBn = (nT - alpha * gh) * rc2;
                float sTn = sB * c, sBn = sT * c;
                sT = sTn; sB = sBn; nT = nTn; nB = nBn;
            }
            // ============ odd round: pair (B_t, T_{t+1}); lane31 idle ============
            {
                // pass 1: dot(B, T_shifted)
                u64 g0 = pk(0.f, 0.f), g1 = g0, g2 = g0, g3 = g0;
#pragma unroll
                for (int k = 0; k < 8; k++) {
                    u64 t0 = __shfl_down_sync(FULL, T[4 * k], 1);
                    u64 t1 = __shfl_down_sync(FULL, T[4 * k + 1], 1);
                    u64 t2 = __shfl_down_sync(FULL, T[4 * k + 2], 1);
                    u64 t3 = __shfl_down_sync(FULL, T[4 * k + 3], 1);
                    g0 = fma2(B[4 * k],     t0, g0);
                    g1 = fma2(B[4 * k + 1], t1, g1);
                    g2 = fma2(B[4 * k + 2], t2, g2);
                    g3 = fma2(B[4 * k + 3], t3, g3);
                }
                float gh = psum(g0) + psum(g1) + psum(g2) + psum(g3);
                float sTm = __shfl_down_sync(FULL, sT, 1);
                float nTm = __shfl_down_sync(FULL, nT, 1);

                float alpha = 0.f, beta = 0.f, c = 1.f, rc2 = 1.f;
                bool rot = (lane < 31) &&
                           (fabsf(gh) > TAU * sqrtf(nB) * sqrtf(nTm));
                if (rot) {
                    float ga = sB * sTm * gh;
                    float nPa = sB * sB * nB, nQa = sTm * sTm * nTm;
                    float zeta = __fdividef(nQa - nPa, 2.0f * ga);
                    float tt = __fdividef(copysignf(1.0f, zeta),
                                          fabsf(zeta) + sqrtf(fmaf(zeta, zeta, 1.0f)));
                    c = rsqrtf(fmaf(tt, tt, 1.0f));
                    rc2 = fmaf(tt, tt, 1.0f);
                    float r = __fdividef(sTm, sB);
                    alpha = tt * r;                 // ship = B - alpha*Tm
                    beta  = __fdividef(tt, r);      // keep = Tm + beta*B
                    any = true;
                }
                // pass 2: recompute shift, rotate, ship P' up; keep Q' locally
                u64 b2 = pk(beta, beta), na2 = pk(-alpha, -alpha);
#pragma unroll
                for (int k = 0; k < 32; k++) {
                    u64 tm = __shfl_down_sync(FULL, T[k], 1);
                    u64 sh = fma2(tm, na2, B[k]);     // P' (goes up to lane+1's top)
                    u64 bn = fma2(B[k], b2, tm);      // Q' (stays as bottom)
                    u64 rc = __shfl_up_sync(FULL, sh, 1);
                    if (lane < 31) B[k] = bn;
                    if (lane >= 1) T[k] = rc;
                }
                float shipS = sB * c, shipN = (nB - alpha * gh) * rc2;
                float keepS = sTm * c, keepN = (nTm + beta * gh) * rc2;
                float rS = __shfl_up_sync(FULL, shipS, 1);
                float rN = __shfl_up_sync(FULL, shipN, 1);
                if (lane < 31) { sB = keepS; nB = keepN; }
                if (lane >= 1) { sT = rS; nT = rN; }
            }
        }
        if (!__any_sync(FULL, any)) break;
    }

    // ---- finalize: fold scales, exact norms, stash W + dsc in shared ----
    float ssT, ssB;
    {
        u64 s1 = pk(sT, sT), s2 = pk(sB, sB);
        u64 a0 = pk(0.f, 0.f), a1 = a0, b0 = a0, b1 = a0;
#pragma unroll
        for (int k = 0; k < 16; k++) {
            T[2 * k] = mul2(T[2 * k], s1); T[2 * k + 1] = mul2(T[2 * k + 1], s1);
            B[2 * k] = mul2(B[2 * k], s2); B[2 * k + 1] = mul2(B[2 * k + 1], s2);
            a0 = fma2(T[2 * k], T[2 * k], a0); a1 = fma2(T[2 * k + 1], T[2 * k + 1], a1);
            b0 = fma2(B[2 * k], B[2 * k], b0); b1 = fma2(B[2 * k + 1], B[2 * k + 1], b1);
        }
        ssT = psum(a0) + psum(a1);
        ssB = psum(b0) + psum(b1);
    }
    {
        u64* c0 = reinterpret_cast<u64*>(Wsh + (2 * lane) * CPAD);
        u64* c1 = reinterpret_cast<u64*>(Wsh + (2 * lane + 1) * CPAD);
#pragma unroll
        for (int k = 0; k < 32; k++) { c0[k] = T[k]; c1[k] = B[k]; }
        float s0 = fmaxf(ssT, 1e-30f);
        Wsh[(2 * lane) * CPAD + 64] = __fdividef(logf(sqrtf(s0) + 1e-9f), s0);
        float s1 = fmaxf(ssB, 1e-30f);
        Wsh[(2 * lane + 1) * CPAD + 64] = __fdividef(logf(sqrtf(s1) + 1e-9f), s1);
    }
    __syncwarp();

    // ---- out = sum_c dsc_c * w_c w_c^T : lane computes rows 2*lane, 2*lane+1 ----
    {
        u64 a0[32], a1[32];
#pragma unroll
        for (int k = 0; k < 32; k++) { a0[k] = pk(0.f, 0.f); a1[k] = pk(0.f, 0.f); }
#pragma unroll 4
        for (int cidx = 0; cidx < N; cidx++) {
            const float* col = Wsh + cidx * CPAD;
            float dc = col[64];
            float2 wi = *reinterpret_cast<const float2*>(col + 2 * lane);
            float u0 = wi.x * dc, u1 = wi.y * dc;
            u64 u02 = pk(u0, u0), u12 = pk(u1, u1);
#pragma unroll
            for (int k = 0; k < 16; k++) {
                ulonglong2 q = *reinterpret_cast<const ulonglong2*>(col + 4 * k);
                a0[2 * k]     = fma2(u02, q.x, a0[2 * k]);
                a0[2 * k + 1] = fma2(u02, q.y, a0[2 * k + 1]);
                a1[2 * k]     = fma2(u12, q.x, a1[2 * k]);
                a1[2 * k + 1] = fma2(u12, q.y, a1[2 * k + 1]);
            }
        }
        float* o0 = out + (long long)m * (N * N) + (2 * lane) * N;
        float* o1 = o0 + N;
#pragma unroll
        for (int k = 0; k < 16; k++) {
            ulonglong2 v0; v0.x = a0[2 * k]; v0.y = a0[2 * k + 1];
            *reinterpret_cast<ulonglong2*>(o0 + 4 * k) = v0;
            ulonglong2 v1; v1.x = a1[2 * k]; v1.y = a1[2 * k + 1];
            *reinterpret_cast<ulonglong2*>(o1 + 4 * k) = v1;
        }
    }
}

}  // namespace

extern "C" void kernel_launch(void* const* d_in, const int* in_sizes, int n_in,
                              void* d_out, int out_size) {
    const float* in = (const float*)d_in[0];
    float* out = (float*)d_out;
    const int nmat = in_sizes[0] / (N * N);   // 8192
    const int smem = WARPS * N * CPAD * (int)sizeof(float);   // 208,896 B
    cudaFuncSetAttribute(logm_warpjac, cudaFuncAttributeMaxDynamicSharedMemorySize, smem);
    const int grid = (nmat + WARPS - 1) / WARPS;
    logm_warpjac<<<grid, THREADS, smem>>>(in, out, nmat);
}